// round 7
// baseline (speedup 1.0000x reference)
#include <cuda_runtime.h>
#include <math.h>

#define Nn 50000
#define Ee 800000
#define Dd 128
#define Gg 500
#define NSs 100
#define M0 64
#define SLOPE 0.2f
#define BN_EPS 1e-5f

#define SCAN_BLK 512
#define SCAN_NB ((Nn + SCAN_BLK - 1) / SCAN_BLK)   // 98

// -------- scratch (device globals; no allocation allowed) --------
// NOTE: host code must NEVER pass these names directly as kernel args —
// that yields the host shadow address (silently "works" on GB300 via ATS,
// hitting host memory). Always cudaGetSymbolAddress first.
__device__ float g_xl[Nn * Dd];
__device__ float g_xr[Nn * Dd];
__device__ float g_h1[Nn * Dd];
__device__ float g_h2[Nn * Dd];
__device__ float g_pooled[Gg * Dd];
__device__ int   g_src[Ee];
__device__ int   g_dst[Ee];
__device__ int   g_counts[Nn];
__device__ int   g_incl[Nn];
__device__ int   g_rowPtr[Nn + 1];
__device__ int   g_head[Nn];
__device__ int   g_csr_src[Ee];
__device__ int   g_blockSums[SCAN_NB + 8];
__device__ int   g_blockOff[SCAN_NB + 8];
__device__ int   g_gcounts[Gg];
__device__ int   g_gstart[Gg + 1];

// ---------------- edge decode: handle int32 OR int64 graph_data ----------------
__global__ void k_decode(const int* __restrict__ gd) {
    int i = blockIdx.x * blockDim.x + threadIdx.x;
    if (i >= Ee) return;
    bool w64 = (gd[1] == 0 && gd[3] == 0 && gd[5] == 0 && gd[7] == 0);
    if (w64) {
        g_src[i] = gd[2 * i];
        g_dst[i] = gd[2 * Ee + 2 * i];
    } else {
        g_src[i] = gd[i];
        g_dst[i] = gd[Ee + i];
    }
}

// ---------------- init ----------------
__global__ void k_zero() {
    int i = blockIdx.x * blockDim.x + threadIdx.x;
    if (i < Nn) g_counts[i] = 0;
    if (i < Gg) g_gcounts[i] = 0;
}

// ---------------- histograms ----------------
__global__ void k_hist_edges() {
    int i = blockIdx.x * blockDim.x + threadIdx.x;
    if (i < Ee) atomicAdd(&g_counts[g_dst[i]], 1);
}
__global__ void k_hist_batch(const int* __restrict__ batch) {
    int i = blockIdx.x * blockDim.x + threadIdx.x;
    if (i < Nn) atomicAdd(&g_gcounts[batch[i]], 1);
}

// ---------------- scan (counts -> rowPtr) ----------------
__global__ void k_scan1() {
    __shared__ int s[SCAN_BLK];
    int tid = threadIdx.x;
    int i = blockIdx.x * SCAN_BLK + tid;
    int v = (i < Nn) ? g_counts[i] : 0;
    s[tid] = v;
    __syncthreads();
    for (int off = 1; off < SCAN_BLK; off <<= 1) {
        int add = (tid >= off) ? s[tid - off] : 0;
        __syncthreads();
        s[tid] += add;
        __syncthreads();
    }
    if (i < Nn) g_incl[i] = s[tid];
    if (tid == SCAN_BLK - 1) g_blockSums[blockIdx.x] = s[tid];
}
__global__ void k_scan2() {
    if (threadIdx.x == 0 && blockIdx.x == 0) {
        int run = 0;
        for (int b = 0; b < SCAN_NB; b++) {
            g_blockOff[b] = run;
            run += g_blockSums[b];
        }
    }
}
__global__ void k_scan3() {
    int i = blockIdx.x * blockDim.x + threadIdx.x;
    if (i < Nn) {
        int tot = g_incl[i] + g_blockOff[i / SCAN_BLK];
        int excl = tot - g_counts[i];
        g_rowPtr[i] = excl;
        g_head[i] = excl;
        if (i == Nn - 1) g_rowPtr[Nn] = tot;
    }
}
__global__ void k_gscan() {
    if (threadIdx.x == 0 && blockIdx.x == 0) {
        int run = 0;
        for (int g = 0; g < Gg; g++) { g_gstart[g] = run; run += g_gcounts[g]; }
        g_gstart[Gg] = run;
    }
}
__global__ void k_fill() {
    int i = blockIdx.x * blockDim.x + threadIdx.x;
    if (i < Ee) {
        int pos = atomicAdd(&g_head[g_dst[i]], 1);
        g_csr_src[pos] = g_src[i];
    }
}

// ---------------- node GEMM: C[nrows,128] = A @ W + bias ----------------
__global__ void k_gemm_node(const float* __restrict__ A, const float* __restrict__ W,
                            const float* __restrict__ bias, float* __restrict__ C,
                            int nrows) {
    __shared__ float As[16][65];
    __shared__ float Bs[16][64];
    int t = threadIdx.x;
    int tx = t & 15, ty = t >> 4;
    int row0 = blockIdx.x * 64;
    int col0 = blockIdx.y * 64;
    float acc[4][4] = {};
    for (int k0 = 0; k0 < 128; k0 += 16) {
#pragma unroll
        for (int i = 0; i < 4; i++) {
            int e = t + i * 256;
            int r = e >> 4, kk = e & 15;
            int gr = row0 + r;
            As[kk][r] = (gr < nrows) ? A[gr * 128 + k0 + kk] : 0.f;
        }
#pragma unroll
        for (int i = 0; i < 4; i++) {
            int e = t + i * 256;
            int kk = e >> 6, c = e & 63;
            Bs[kk][c] = W[(k0 + kk) * 128 + col0 + c];
        }
        __syncthreads();
#pragma unroll
        for (int kk = 0; kk < 16; kk++) {
            float a[4], b[4];
#pragma unroll
            for (int r = 0; r < 4; r++) a[r] = As[kk][ty * 4 + r];
#pragma unroll
            for (int c = 0; c < 4; c++) b[c] = Bs[kk][tx * 4 + c];
#pragma unroll
            for (int r = 0; r < 4; r++)
#pragma unroll
                for (int c = 0; c < 4; c++) acc[r][c] += a[r] * b[c];
        }
        __syncthreads();
    }
#pragma unroll
    for (int r = 0; r < 4; r++) {
        int gr = row0 + ty * 4 + r;
        if (gr < nrows) {
#pragma unroll
            for (int c = 0; c < 4; c++) {
                int gc = col0 + tx * 4 + c;
                C[gr * 128 + gc] = acc[r][c] + bias[gc];
            }
        }
    }
}

// ---------------- GATv2 aggregate: warp per destination node ----------------
__global__ void k_aggregate(const float* __restrict__ xl, const float* __restrict__ xr,
                            const float* __restrict__ att, const float* __restrict__ bias,
                            float* __restrict__ out,
                            int do_bn,
                            const float* __restrict__ gamma, const float* __restrict__ beta,
                            const float* __restrict__ mean, const float* __restrict__ var) {
    int warpId = (blockIdx.x * blockDim.x + threadIdx.x) >> 5;
    if (warpId >= Nn) return;
    int lane = threadIdx.x & 31;
    int d = warpId;
    int s0 = g_rowPtr[d], s1 = g_rowPtr[d + 1];

    float xrv[4], attv[4];
#pragma unroll
    for (int i = 0; i < 4; i++) {
        xrv[i] = xr[d * 128 + lane + 32 * i];
        attv[i] = att[lane + 32 * i];
    }

    // sweep 1: max logit
    float m = -INFINITY;
    for (int p = s0; p < s1; p++) {
        int src = g_csr_src[p];
        const float* row = xl + src * 128;
        float partial = 0.f;
#pragma unroll
        for (int i = 0; i < 4; i++) {
            float v = row[lane + 32 * i] + xrv[i];
            float lr = v > 0.f ? v : SLOPE * v;
            partial += lr * attv[i];
        }
#pragma unroll
        for (int o = 16; o; o >>= 1) partial += __shfl_xor_sync(0xffffffffu, partial, o);
        m = fmaxf(m, partial);
    }

    // sweep 2: exp, denom, weighted sum
    float denom = 0.f;
    float acc[4] = {0.f, 0.f, 0.f, 0.f};
    for (int p = s0; p < s1; p++) {
        int src = g_csr_src[p];
        const float* row = xl + src * 128;
        float rowv[4];
        float partial = 0.f;
#pragma unroll
        for (int i = 0; i < 4; i++) {
            rowv[i] = row[lane + 32 * i];
            float v = rowv[i] + xrv[i];
            float lr = v > 0.f ? v : SLOPE * v;
            partial += lr * attv[i];
        }
#pragma unroll
        for (int o = 16; o; o >>= 1) partial += __shfl_xor_sync(0xffffffffu, partial, o);
        float pe = expf(partial - m);
        denom += pe;
#pragma unroll
        for (int i = 0; i < 4; i++) acc[i] += pe * rowv[i];
    }

    float inv = (s1 > s0) ? 1.f / denom : 0.f;
#pragma unroll
    for (int i = 0; i < 4; i++) {
        int f = lane + 32 * i;
        float o = acc[i] * inv + bias[f];
        if (do_bn) {
            float sc = gamma[f] * rsqrtf(var[f] + BN_EPS);
            o = (o - mean[f]) * sc + beta[f];
            o = fmaxf(o, 0.f);
        }
        out[d * 128 + f] = o;
    }
}

// ---------------- pooling: block per graph (batch is sorted) ----------------
__global__ void k_pool() {
    int g = blockIdx.x;
    int t = threadIdx.x;   // 128
    int s = g_gstart[g], e = g_gstart[g + 1];
    float sum = 0.f;
    for (int r = s; r < e; r++) sum += g_h2[r * 128 + t];
    int cnt = e - s;
    g_pooled[g * 128 + t] = sum / (float)(cnt > 0 ? cnt : 1);
}

// ---------------- fused head: fc1(+bias,relu) GEMM tile + fc3 + sigmoid ----------------
// grid: (ceil(G/64), NS); block 256. Tile: 64 graphs x one stock (64 cols), K=128.
__global__ void k_head(const float* __restrict__ fc1w, const float* __restrict__ fc1b,
                       const float* __restrict__ fc3w, const float* __restrict__ fc3b,
                       float* __restrict__ out) {
    __shared__ float As[16][65];
    __shared__ float Bs[16][64];
    __shared__ float red[64][17];
    int t = threadIdx.x;
    int tx = t & 15, ty = t >> 4;
    int g0 = blockIdx.x * 64;
    int s = blockIdx.y;           // stock
    int colBase = s * 64;
    float acc[4][4] = {};
    for (int k0 = 0; k0 < 128; k0 += 16) {
#pragma unroll
        for (int i = 0; i < 4; i++) {
            int e = t + i * 256;
            int r = e >> 4, kk = e & 15;
            int gg = g0 + r;
            As[kk][r] = (gg < Gg) ? g_pooled[gg * 128 + k0 + kk] : 0.f;
        }
#pragma unroll
        for (int i = 0; i < 4; i++) {
            int e = t + i * 256;
            int kk = e >> 6, c = e & 63;
            Bs[kk][c] = fc1w[(k0 + kk) * (NSs * M0) + colBase + c];
        }
        __syncthreads();
#pragma unroll
        for (int kk = 0; kk < 16; kk++) {
            float a[4], b[4];
#pragma unroll
            for (int r = 0; r < 4; r++) a[r] = As[kk][ty * 4 + r];
#pragma unroll
            for (int c = 0; c < 4; c++) b[c] = Bs[kk][tx * 4 + c];
#pragma unroll
            for (int r = 0; r < 4; r++)
#pragma unroll
                for (int c = 0; c < 4; c++) acc[r][c] += a[r] * b[c];
        }
        __syncthreads();
    }
    // per-row partial fc3 dot
#pragma unroll
    for (int r = 0; r < 4; r++) {
        float p = 0.f;
#pragma unroll
        for (int c = 0; c < 4; c++) {
            int j = tx * 4 + c;
            float v = acc[r][c] + fc1b[colBase + j];
            v = fmaxf(v, 0.f);
            p += v * fc3w[j];
        }
        red[ty * 4 + r][tx] = p;
    }
    __syncthreads();
    if (t < 64) {
        float v = 0.f;
#pragma unroll
        for (int i = 0; i < 16; i++) v += red[t][i];
        v += fc3b[0];
        float o = 1.f / (1.f + expf(-v));
        int g = g0 + t;
        if (g < Gg) out[g * NSs + s] = o;
    }
}

// ---------------- launch ----------------
extern "C" void kernel_launch(void* const* d_in, const int* in_sizes, int n_in,
                              void* d_out, int out_size) {
    const float* x     = (const float*)d_in[0];
    const int*   gd    = (const int*)d_in[1];
    const int*   batch = (const int*)d_in[2];
    const float* wl0   = (const float*)d_in[3];
    const float* bl0   = (const float*)d_in[4];
    const float* wr0   = (const float*)d_in[5];
    const float* br0   = (const float*)d_in[6];
    const float* att0  = (const float*)d_in[7];
    const float* b0    = (const float*)d_in[8];
    const float* wl1   = (const float*)d_in[9];
    const float* bl1   = (const float*)d_in[10];
    const float* wr1   = (const float*)d_in[11];
    const float* br1   = (const float*)d_in[12];
    const float* att1  = (const float*)d_in[13];
    const float* b1    = (const float*)d_in[14];
    const float* bn_g  = (const float*)d_in[15];
    const float* bn_b  = (const float*)d_in[16];
    const float* bn_m  = (const float*)d_in[17];
    const float* bn_v  = (const float*)d_in[18];
    const float* fc1w  = (const float*)d_in[19];
    const float* fc1b  = (const float*)d_in[20];
    const float* fc3w  = (const float*)d_in[21];
    const float* fc3b  = (const float*)d_in[22];
    float* out = (float*)d_out;

    // REAL device addresses of the scratch globals (host-side symbol names
    // resolve to host shadows which GB300's ATS silently serves — the round
    // 1-6 bug). cudaGetSymbolAddress is an immediate API, graph-capture safe.
    float *p_xl, *p_xr, *p_h1, *p_h2;
    cudaGetSymbolAddress((void**)&p_xl, g_xl);
    cudaGetSymbolAddress((void**)&p_xr, g_xr);
    cudaGetSymbolAddress((void**)&p_h1, g_h1);
    cudaGetSymbolAddress((void**)&p_h2, g_h2);

    // decode edges + CSR build + graph ranges
    k_decode<<<(Ee + 255) / 256, 256>>>(gd);
    k_zero<<<(Nn + 255) / 256, 256>>>();
    k_hist_edges<<<(Ee + 255) / 256, 256>>>();
    k_hist_batch<<<(Nn + 255) / 256, 256>>>(batch);
    k_scan1<<<SCAN_NB, SCAN_BLK>>>();
    k_scan2<<<1, 1>>>();
    k_scan3<<<(Nn + 255) / 256, 256>>>();
    k_gscan<<<1, 1>>>();
    k_fill<<<(Ee + 255) / 256, 256>>>();

    dim3 ggrid((Nn + 63) / 64, 2);
    // layer 0
    k_gemm_node<<<ggrid, 256>>>(x, wl0, bl0, p_xl, Nn);
    k_gemm_node<<<ggrid, 256>>>(x, wr0, br0, p_xr, Nn);
    k_aggregate<<<(Nn * 32 + 255) / 256, 256>>>(p_xl, p_xr, att0, b0, p_h1,
                                                1, bn_g, bn_b, bn_m, bn_v);
    // layer 1
    k_gemm_node<<<ggrid, 256>>>(p_h1, wl1, bl1, p_xl, Nn);
    k_gemm_node<<<ggrid, 256>>>(p_h1, wr1, br1, p_xr, Nn);
    k_aggregate<<<(Nn * 32 + 255) / 256, 256>>>(p_xl, p_xr, att1, b1, p_h2,
                                                0, (const float*)0, (const float*)0,
                                                (const float*)0, (const float*)0);
    // pool + head
    k_pool<<<Gg, 128>>>();
    dim3 hgrid((Gg + 63) / 64, NSs);
    k_head<<<hgrid, 256>>>(fc1w, fc1b, fc3w, fc3b, out);
    (void)in_sizes; (void)n_in; (void)out_size;
}